// round 15
// baseline (speedup 1.0000x reference)
#include <cuda_runtime.h>

#define LNUM 3
#define ENUM 1000000
#define NNODE 100000
#define DDIM 64
#define ADIM 8
#define NR2C 461
#define QNUM 1000
#define ENTC 10000

// ---------------- scratch (device globals; no allocation) ----------------
__device__ float g_state[NNODE * DDIM];
__device__ float g_agg[NNODE * DDIM];      // zero at load; re-zeroed by k_fused each layer
__device__ float g_nproj[NNODE * ADIM];
__device__ float g_rproj[LNUM * NR2C * ADIM];
__device__ float g_qproj[LNUM * QNUM * ADIM];
__device__ float g_bWh[LNUM * 4096];       // [ks][wc][lane][4]: cg0(j0,j1), cg1(j0,j1)
__device__ float g_bG[24576];              // [ks][ntg][lane][4]: Wih(j0,j1), Whh(j0,j1)
__device__ float g_bGi[12288];             // [ks][ntg][lane][2]: Wih only (dense, FIRST)
__device__ float g_bWs[LNUM * 512];
__device__ float g_scores[NNODE];
__device__ int   g_winner[QNUM * ENTC];    // zero at load; winner(+1) reset by k_finish
__device__ int4  g_ep4[(size_t)LNUM * ENUM];  // packed (sub, rel, ridx, obj)

// ---------------- helpers ----------------
__device__ __forceinline__ unsigned f2tf(float x) {
    unsigned u;
    asm("cvt.rna.tf32.f32 %0, %1;" : "=r"(u) : "f"(x));
    return u;
}
__device__ __forceinline__ float tf(float x) { return __uint_as_float(f2tf(x)); }
__device__ __forceinline__ float sigf(float x) { return 1.f / (1.f + __expf(-x)); }

__device__ __forceinline__ void mma8(float acc[4], unsigned a0, unsigned a1,
                                     unsigned a2, unsigned a3, unsigned b0, unsigned b1) {
    asm volatile(
        "mma.sync.aligned.m16n8k8.row.col.f32.tf32.tf32.f32 "
        "{%0,%1,%2,%3}, {%4,%5,%6,%7}, {%8,%9}, {%0,%1,%2,%3};"
        : "+f"(acc[0]), "+f"(acc[1]), "+f"(acc[2]), "+f"(acc[3])
        : "r"(a0), "r"(a1), "r"(a2), "r"(a3), "r"(b0), "r"(b1));
}

// ---------------- packed edge indices (pure function of inputs) --------------
__global__ void k_pack(const int* __restrict__ sub, const int* __restrict__ rel,
                       const int* __restrict__ ridx, const int* __restrict__ obj) {
    int i = blockIdx.x * blockDim.x + threadIdx.x;
    if (i >= LNUM * ENUM) return;
    g_ep4[i] = make_int4(__ldg(sub + i), __ldg(rel + i), __ldg(ridx + i), __ldg(obj + i));
}

// ---------------- init: zero output + packed weight fragments ----------------
__global__ void k_init(float4* out4, const float* __restrict__ Wh,
                       const float* __restrict__ Wih, const float* __restrict__ Whh,
                       const float* __restrict__ Ws) {
    int i = blockIdx.x * blockDim.x + threadIdx.x;
    if (i < QNUM * ENTC / 4) out4[i] = make_float4(0.f, 0.f, 0.f, 0.f);
    const int NWH = LNUM * 4096, NG = 24576, NWS = LNUM * 512, NGI = 12288;
    if (i < NWH) {
        int layer = i >> 12, ii = i & 4095;
        int e = ii & 3, lane = (ii >> 2) & 31, wc = (ii >> 7) & 3, ks = ii >> 9;
        int ntg = wc * 2 + (e >> 1), j = e & 1;
        int n = ntg * 8 + (lane >> 2), k = ks * 8 + (lane & 3) + 4 * j;
        g_bWh[i] = tf(Wh[layer * 4096 + n * 64 + k]);
    } else if (i < NWH + NG) {
        int ii = i - NWH;
        int e = ii & 3, lane = (ii >> 2) & 31;
        int ng = ii >> 7;
        int ntg = ng % 24, ks = ng / 24;
        int j = e & 1;
        const float* src = (e < 2) ? Wih : Whh;
        int n = ntg * 8 + (lane >> 2), k = ks * 8 + (lane & 3) + 4 * j;
        g_bG[ii] = tf(src[n * 64 + k]);
    } else if (i < NWH + NG + NWS) {
        int ii = i - NWH - NG;
        int layer = ii / 512, e = ii % 512;
        int j = e & 1, lane = (e >> 1) & 31, ks = e >> 6;
        int n = lane >> 2, k = ks * 8 + (lane & 3) + 4 * j;
        g_bWs[ii] = tf(Ws[layer * 512 + n * 64 + k]);
    } else if (i < NWH + NG + NWS + NGI) {
        int ii = i - NWH - NG - NWS;
        int j = ii & 1, lane = (ii >> 1) & 31;
        int ng = ii >> 6;
        int ntg = ng % 24, ks = ng / 24;
        int n = ntg * 8 + (lane >> 2), k = ks * 8 + (lane & 3) + 4 * j;
        g_bGi[ii] = tf(Wih[n * 64 + k]);
    }
}

// ---------------- rel/query projections for ALL layers ----------------
__global__ void k_projRQ(const float* __restrict__ rela, const float* __restrict__ Wr,
                         const float* __restrict__ Wqr, const float* __restrict__ Wqrb,
                         const int* __restrict__ relation) {
    int w = (blockIdx.x * blockDim.x + threadIdx.x) >> 5;
    int lane = threadIdx.x & 31;
    const int PER = NR2C + QNUM;
    if (w >= LNUM * PER) return;
    int layer = w / PER;
    int r = w % PER;
    const float* emb = rela + (size_t)layer * NR2C * DDIM;
    const float* src;
    const float* W;
    float* dst;
    bool isQ;
    if (r < NR2C) {
        src = emb + (size_t)r * 64; W = Wr + layer * 512;
        dst = g_rproj + (layer * NR2C + r) * 8; isQ = false;
    } else {
        int q = r - NR2C;
        src = emb + (size_t)__ldg(relation + q) * 64; W = Wqr + layer * 512;
        dst = g_qproj + (layer * QNUM + q) * 8; isQ = true;
    }
    float2 s2 = ((const float2*)src)[lane];
    float res = 0.f;
#pragma unroll
    for (int a = 0; a < 8; a++) {
        float2 w2 = __ldg((const float2*)(W + a * 64) + lane);
        float p = s2.x * w2.x + s2.y * w2.y;
#pragma unroll
        for (int m = 16; m >= 1; m >>= 1) p += __shfl_xor_sync(0xffffffffu, p, m);
        if (lane == a) res = p;
    }
    if (lane < 8) dst[lane] = res + (isQ ? __ldg(Wqrb + layer * 8 + lane) : 0.f);
}

// ---------------- edge kernel: 16 lanes/edge, packed indices -----------------
template <bool HS>
__global__ void k_edge(const int4* __restrict__ ep4, const float* __restrict__ emb,
                       const float* __restrict__ wal, const float* __restrict__ walb,
                       const float* __restrict__ rproj, const float* __restrict__ qproj) {
    int gt = blockIdx.x * blockDim.x + threadIdx.x;
    int e = gt >> 4;
    int sl = threadIdx.x & 15;
    int4 ei = __ldg(ep4 + e);           // (sub, rel, ridx, obj) broadcast within group
    int s = ei.x, r = ei.y, q = ei.z, o = ei.w;

    float p = 0.f;
    if (sl < 8) {
        float t = __ldg(rproj + r * 8 + sl) + __ldg(qproj + q * 8 + sl);
        if (HS) t += g_nproj[s * 8 + sl];
        p = fmaxf(t, 0.f) * __ldg(wal + sl);
    }
    p += __shfl_xor_sync(0xffffffffu, p, 1);
    p += __shfl_xor_sync(0xffffffffu, p, 2);
    p += __shfl_xor_sync(0xffffffffu, p, 4);
    p += __shfl_xor_sync(0xffffffffu, p, 8);
    float alpha = sigf(p + __ldg(walb));

    float4 hr = __ldg((const float4*)emb + r * 16 + sl);
    if (HS) {
        float4 hs = __ldg((const float4*)g_state + (size_t)s * 16 + sl);
        asm volatile("red.global.add.v4.f32 [%0], {%1,%2,%3,%4};"
                     :: "l"(g_agg + (size_t)o * 64 + sl * 4),
                        "f"(alpha * (hs.x + hr.x)), "f"(alpha * (hs.y + hr.y)),
                        "f"(alpha * (hs.z + hr.z)), "f"(alpha * (hs.w + hr.w))
                     : "memory");
    } else {
        asm volatile("red.global.add.v4.f32 [%0], {%1,%2,%3,%4};"
                     :: "l"(g_agg + (size_t)o * 64 + sl * 4),
                        "f"(alpha * hr.x), "f"(alpha * hr.y),
                        "f"(alpha * hr.z), "f"(alpha * hr.w) : "memory");
    }
}

// ---------------- fused node phase (+nproj, +score, re-zero agg) -------------
// FIRST (light) layer prefers occ=2/128 regs; heavy layers prefer occ=3.
template <bool FIRST, bool PROJ, bool SCORE>
__global__ void __launch_bounds__(256, FIRST ? 2 : 3)
k_fused(const float* __restrict__ BWh, const float* __restrict__ BG,
        const float* __restrict__ BGi, const float* __restrict__ BWs,
        const float* __restrict__ bih, const float* __restrict__ bhh,
        const float* __restrict__ wf, const int* __restrict__ nq,
        const int* __restrict__ ne) {
    __shared__ float As[32][68];
    __shared__ float Ss[32][68];
    __shared__ float sbuf[32];
    int t = threadIdx.x;
    int warp = t >> 5, lane = t & 31;
    int wr = warp >> 2, wc = warp & 3;
    int tg = lane >> 2, tig = lane & 3;
    int m0 = blockIdx.x * 32;

    if (SCORE && t < 32) sbuf[t] = 0.f;

#pragma unroll
    for (int p = 0; p < 2; p++) {
        int idx = t + p * 256;
        int r = idx >> 4, c4 = idx & 15;
        float4 v = *((const float4*)(g_agg + (size_t)(m0 + r) * 64) + c4);
        As[r][c4 * 4 + 0] = tf(v.x);
        As[r][c4 * 4 + 1] = tf(v.y);
        As[r][c4 * 4 + 2] = tf(v.z);
        As[r][c4 * 4 + 3] = tf(v.w);
        if (!FIRST) {
            float4 s = *((const float4*)(g_state + (size_t)(m0 + r) * 64) + c4);
            Ss[r][c4 * 4 + 0] = tf(s.x);
            Ss[r][c4 * 4 + 1] = tf(s.y);
            Ss[r][c4 * 4 + 2] = tf(s.z);
            Ss[r][c4 * 4 + 3] = tf(s.w);
        }
    }
    __syncthreads();

    // zero this block's agg slice for the next layer / next replay
    {
        float4* a4 = (float4*)(g_agg + (size_t)m0 * 64);
        float4 z = make_float4(0.f, 0.f, 0.f, 0.f);
        a4[t] = z;
        a4[t + 256] = z;
    }

    // --- X = relu(agg @ Wh^T); result written back into As ---
    {
        float accx[2][4] = {};
#pragma unroll
        for (int ks = 0; ks < 8; ks++) {
            int k0 = ks * 8;
            unsigned a0 = __float_as_uint(As[wr * 16 + tg][k0 + tig]);
            unsigned a1 = __float_as_uint(As[wr * 16 + tg + 8][k0 + tig]);
            unsigned a2 = __float_as_uint(As[wr * 16 + tg][k0 + tig + 4]);
            unsigned a3 = __float_as_uint(As[wr * 16 + tg + 8][k0 + tig + 4]);
            float4 b = __ldg((const float4*)BWh + (ks * 4 + wc) * 32 + lane);
            mma8(accx[0], a0, a1, a2, a3, __float_as_uint(b.x), __float_as_uint(b.y));
            mma8(accx[1], a0, a1, a2, a3, __float_as_uint(b.z), __float_as_uint(b.w));
        }
        __syncthreads();  // all mma reads of As complete before overwrite
        int rl = wr * 16 + tg;
#pragma unroll
        for (int cg = 0; cg < 2; cg++) {
            int col = (wc * 2 + cg) * 8 + 2 * tig;
            As[rl][col]         = tf(fmaxf(accx[cg][0], 0.f));
            As[rl][col + 1]     = tf(fmaxf(accx[cg][1], 0.f));
            As[rl + 8][col]     = tf(fmaxf(accx[cg][2], 0.f));
            As[rl + 8][col + 1] = tf(fmaxf(accx[cg][3], 0.f));
        }
        __syncthreads();
    }

    // --- gates (X read from As; packed fragments) ---
    float acc_r[2][4] = {}, acc_z[2][4] = {}, acc_ni[2][4] = {}, acc_nh[2][4] = {};
#pragma unroll
    for (int ks = 0; ks < 8; ks++) {
        int k0 = ks * 8;
        unsigned x0 = __float_as_uint(As[wr * 16 + tg][k0 + tig]);
        unsigned x1 = __float_as_uint(As[wr * 16 + tg + 8][k0 + tig]);
        unsigned x2 = __float_as_uint(As[wr * 16 + tg][k0 + tig + 4]);
        unsigned x3 = __float_as_uint(As[wr * 16 + tg + 8][k0 + tig + 4]);
        unsigned s0 = 0, s1 = 0, s2 = 0, s3 = 0;
        if (!FIRST) {
            s0 = __float_as_uint(Ss[wr * 16 + tg][k0 + tig]);
            s1 = __float_as_uint(Ss[wr * 16 + tg + 8][k0 + tig]);
            s2 = __float_as_uint(Ss[wr * 16 + tg][k0 + tig + 4]);
            s3 = __float_as_uint(Ss[wr * 16 + tg + 8][k0 + tig + 4]);
        }
#pragma unroll
        for (int cg = 0; cg < 2; cg++) {
            int nb = wc * 2 + cg;
#pragma unroll
            for (int g = 0; g < 3; g++) {
                int ntg = g * 8 + nb;
                float* acc = (g == 0) ? acc_r[cg] : (g == 1) ? acc_z[cg] : acc_ni[cg];
                if (FIRST) {
                    float2 b = __ldg((const float2*)BGi + (ks * 24 + ntg) * 32 + lane);
                    mma8(acc, x0, x1, x2, x3, __float_as_uint(b.x), __float_as_uint(b.y));
                } else {
                    float4 b = __ldg((const float4*)BG + (ks * 24 + ntg) * 32 + lane);
                    mma8(acc, x0, x1, x2, x3, __float_as_uint(b.x), __float_as_uint(b.y));
                    float* acch = (g == 0) ? acc_r[cg] : (g == 1) ? acc_z[cg] : acc_nh[cg];
                    mma8(acch, s0, s1, s2, s3, __float_as_uint(b.z), __float_as_uint(b.w));
                }
            }
        }
    }

    if (PROJ) __syncthreads();  // gate-mma reads of Ss done before overwrite

    // --- GRU epilogue ---
    int r0 = m0 + wr * 16 + tg;
    float ps0 = 0.f, ps1 = 0.f;
#pragma unroll
    for (int cg = 0; cg < 2; cg++) {
        int col = (wc * 2 + cg) * 8 + 2 * tig;
        float2 bi_r = __ldg((const float2*)(bih + col));
        float2 bh_r = __ldg((const float2*)(bhh + col));
        float2 bi_z = __ldg((const float2*)(bih + 64 + col));
        float2 bh_z = __ldg((const float2*)(bhh + 64 + col));
        float2 bi_n = __ldg((const float2*)(bih + 128 + col));
        float2 bh_n = __ldg((const float2*)(bhh + 128 + col));
        float2 h0v = make_float2(0.f, 0.f), h1v = make_float2(0.f, 0.f);
        if (!FIRST) {
            h0v = *(const float2*)(g_state + (size_t)r0 * 64 + col);
            h1v = *(const float2*)(g_state + (size_t)(r0 + 8) * 64 + col);
        }
#define GRU1(ai, bx, hy, outv)                                                  \
        {                                                                       \
            float rr = sigf(acc_r[cg][ai] + bi_r.bx + bh_r.bx);                 \
            float zz = sigf(acc_z[cg][ai] + bi_z.bx + bh_z.bx);                 \
            float nn = tanhf(acc_ni[cg][ai] + bi_n.bx +                         \
                             rr * (acc_nh[cg][ai] + bh_n.bx));                  \
            outv = (1.f - zz) * nn + zz * hy;                                   \
        }
        float2 o0, o1;
        GRU1(0, x, h0v.x, o0.x)
        GRU1(1, y, h0v.y, o0.y)
        GRU1(2, x, h1v.x, o1.x)
        GRU1(3, y, h1v.y, o1.y)
#undef GRU1
        *(float2*)(g_state + (size_t)r0 * 64 + col) = o0;
        *(float2*)(g_state + (size_t)(r0 + 8) * 64 + col) = o1;
        if (PROJ) {
            int rl = wr * 16 + tg;
            Ss[rl][col] = tf(o0.x);
            Ss[rl][col + 1] = tf(o0.y);
            Ss[rl + 8][col] = tf(o1.x);
            Ss[rl + 8][col + 1] = tf(o1.y);
        }
        if (SCORE) {
            float wfa = __ldg(wf + col), wfb = __ldg(wf + col + 1);
            ps0 += o0.x * wfa + o0.y * wfb;
            ps1 += o1.x * wfa + o1.y * wfb;
        }
    }

    if (PROJ) {
        __syncthreads();
        if (warp < 2) {
            float acc[4] = {};
#pragma unroll
            for (int ks = 0; ks < 8; ks++) {
                int k0 = ks * 8;
                unsigned a0 = __float_as_uint(Ss[warp * 16 + tg][k0 + tig]);
                unsigned a1 = __float_as_uint(Ss[warp * 16 + tg + 8][k0 + tig]);
                unsigned a2 = __float_as_uint(Ss[warp * 16 + tg][k0 + tig + 4]);
                unsigned a3 = __float_as_uint(Ss[warp * 16 + tg + 8][k0 + tig + 4]);
                float2 b = *(const float2*)(BWs + ((size_t)ks * 32 + lane) * 2);
                mma8(acc, a0, a1, a2, a3, __float_as_uint(b.x), __float_as_uint(b.y));
            }
            int row = m0 + warp * 16 + tg;
            *(float2*)(g_nproj + row * 8 + 2 * tig) = make_float2(acc[0], acc[1]);
            *(float2*)(g_nproj + (row + 8) * 8 + 2 * tig) = make_float2(acc[2], acc[3]);
        }
    }

    if (SCORE) {
        int rl = wr * 16 + tg;
        atomicAdd(&sbuf[rl], ps0);
        atomicAdd(&sbuf[rl + 8], ps1);
        __syncthreads();
        if (t < 32) {
            int row = m0 + t;
            g_scores[row] = sbuf[t];
            int slot = __ldg(nq + row) * ENTC + __ldg(ne + row);
            atomicMax(&g_winner[slot], row + 1);   // +1: 0 = empty
        }
    }
}

// ---------------- merged scatter + winner reset ----------------
// Unique winner thread writes out and resets its slot; non-winners read either
// the winner value (!= n+1) or 0 (!= any n+1). Deterministic and replay-safe.
__global__ void k_finish(const int* __restrict__ nq, const int* __restrict__ ne,
                         float* __restrict__ out) {
    int n = blockIdx.x * blockDim.x + threadIdx.x;
    if (n >= NNODE) return;
    int slot = __ldg(nq + n) * ENTC + __ldg(ne + n);
    if (g_winner[slot] == n + 1) {
        out[slot] = g_scores[n];
        g_winner[slot] = 0;
    }
}

// ---------------- host launch ----------------
extern "C" void kernel_launch(void* const* d_in, const int* in_sizes, int n_in,
                              void* d_out, int out_size) {
    const int* relation = (const int*)d_in[0];
    const int* r_idx    = (const int*)d_in[1];
    const int* rel      = (const int*)d_in[2];
    const int* sub      = (const int*)d_in[3];
    const int* obj      = (const int*)d_in[4];
    const int* nq       = (const int*)d_in[6];
    const int* ne       = (const int*)d_in[7];
    const float* rela   = (const float*)d_in[8];
    const float* Ws     = (const float*)d_in[9];
    const float* Wr     = (const float*)d_in[10];
    const float* Wqr    = (const float*)d_in[11];
    const float* Wqrb   = (const float*)d_in[12];
    const float* wal    = (const float*)d_in[13];
    const float* walb   = (const float*)d_in[14];
    const float* Wh     = (const float*)d_in[15];
    const float* Wih    = (const float*)d_in[16];
    const float* Whh    = (const float*)d_in[17];
    const float* bih    = (const float*)d_in[18];
    const float* bhh    = (const float*)d_in[19];
    const float* Wfin   = (const float*)d_in[20];
    float* out = (float*)d_out;

    float *p_bWh, *p_bG, *p_bGi, *p_bWs, *p_rproj, *p_qproj;
    int4* p_ep4;
    cudaGetSymbolAddress((void**)&p_bWh, g_bWh);
    cudaGetSymbolAddress((void**)&p_bG, g_bG);
    cudaGetSymbolAddress((void**)&p_bGi, g_bGi);
    cudaGetSymbolAddress((void**)&p_bWs, g_bWs);
    cudaGetSymbolAddress((void**)&p_rproj, g_rproj);
    cudaGetSymbolAddress((void**)&p_qproj, g_qproj);
    cudaGetSymbolAddress((void**)&p_ep4, g_ep4);

    const int TB = 256;
    // launch 0: packed edge indices
    k_pack<<<(LNUM * ENUM + TB - 1) / TB, TB>>>(sub, rel, r_idx, obj);
    // launch 1: out zero + weight fragments
    k_init<<<(QNUM * ENTC / 4 + TB - 1) / TB, TB>>>((float4*)out, Wh, Wih, Whh, Ws);
    // launch 2: rel/query projections
    {
        int W = LNUM * (NR2C + QNUM);
        k_projRQ<<<(W * 32 + TB - 1) / TB, TB>>>(rela, Wr, Wqr, Wqrb, relation);
    }

    const int EG = ENUM * 16 / TB;
    const int FG = NNODE / 32;
    for (int i = 0; i < LNUM; i++) {
        const float* emb = rela + (size_t)i * NR2C * DDIM;
        const float* rp = p_rproj + i * NR2C * ADIM;
        const float* qp = p_qproj + i * QNUM * ADIM;
        const int4* ep = p_ep4 + (size_t)i * ENUM;
        if (i == 0) {
            // launch 3: edge0 (ncu target)
            k_edge<false><<<EG, TB>>>(ep, emb, wal, walb, rp, qp);
            k_fused<true, true, false><<<FG, TB>>>(p_bWh, p_bG, p_bGi, p_bWs + 512,
                                                   bih, bhh, Wfin, nq, ne);
        } else {
            k_edge<true><<<EG, TB>>>(ep, emb, wal + i * 8, walb + i, rp, qp);
            if (i + 1 < LNUM)
                k_fused<false, true, false><<<FG, TB>>>(p_bWh + i * 4096, p_bG, p_bGi,
                                                        p_bWs + (i + 1) * 512,
                                                        bih, bhh, Wfin, nq, ne);
            else
                k_fused<false, false, true><<<FG, TB>>>(p_bWh + i * 4096, p_bG, p_bGi,
                                                        p_bWs, bih, bhh, Wfin, nq, ne);
        }
    }

    k_finish<<<(NNODE + TB - 1) / TB, TB>>>(nq, ne, out);
}

// round 16
// speedup vs baseline: 1.0192x; 1.0192x over previous
#include <cuda_runtime.h>

#define LNUM 3
#define ENUM 1000000
#define NNODE 100000
#define DDIM 64
#define ADIM 8
#define NR2C 461
#define QNUM 1000
#define ENTC 10000

// ---------------- scratch (device globals; no allocation) ----------------
__device__ float g_state[NNODE * DDIM];
__device__ float g_agg[NNODE * DDIM];      // zero at load; re-zeroed by k_fused each layer
__device__ float g_nproj[NNODE * ADIM];
__device__ float g_rproj[LNUM * NR2C * ADIM];
__device__ float g_qproj[LNUM * QNUM * ADIM];
__device__ float g_alpha0[QNUM * NR2C];
__device__ float g_bWh[LNUM * 4096];       // [ks][wc][lane][4]: cg0(j0,j1), cg1(j0,j1)
__device__ float g_bG[24576];              // [ks][ntg][lane][4]: Wih(j0,j1), Whh(j0,j1)
__device__ float g_bGi[12288];             // [ks][ntg][lane][2]: Wih only (dense, FIRST)
__device__ float g_bWs[LNUM * 512];
__device__ float g_scores[NNODE];
__device__ int   g_winner[QNUM * ENTC];    // zero at load; winner(+1) reset by k_finish

// ---------------- helpers ----------------
__device__ __forceinline__ unsigned f2tf(float x) {
    unsigned u;
    asm("cvt.rna.tf32.f32 %0, %1;" : "=r"(u) : "f"(x));
    return u;
}
__device__ __forceinline__ float tf(float x) { return __uint_as_float(f2tf(x)); }
__device__ __forceinline__ float sigf(float x) { return 1.f / (1.f + __expf(-x)); }

__device__ __forceinline__ void mma8(float acc[4], unsigned a0, unsigned a1,
                                     unsigned a2, unsigned a3, unsigned b0, unsigned b1) {
    asm volatile(
        "mma.sync.aligned.m16n8k8.row.col.f32.tf32.tf32.f32 "
        "{%0,%1,%2,%3}, {%4,%5,%6,%7}, {%8,%9}, {%0,%1,%2,%3};"
        : "+f"(acc[0]), "+f"(acc[1]), "+f"(acc[2]), "+f"(acc[3])
        : "r"(a0), "r"(a1), "r"(a2), "r"(a3), "r"(b0), "r"(b1));
}

// ---------------- combined init: projRQ (blocks [0,PB)) + zero/pack rest -----
#define PROJ_BLOCKS 548   // ceil(LNUM*(NR2C+QNUM)*32 / 256)

__global__ void k_init(float4* out4, const float* __restrict__ Wh,
                       const float* __restrict__ Wih, const float* __restrict__ Whh,
                       const float* __restrict__ Ws, const float* __restrict__ rela,
                       const float* __restrict__ Wr, const float* __restrict__ Wqr,
                       const float* __restrict__ Wqrb, const int* __restrict__ relation) {
    int t = threadIdx.x;
    if (blockIdx.x < PROJ_BLOCKS) {
        // --- rel/query projections for all layers ---
        int w = (blockIdx.x * 256 + t) >> 5;
        int lane = t & 31;
        const int PER = NR2C + QNUM;
        if (w >= LNUM * PER) return;
        int layer = w / PER;
        int r = w % PER;
        const float* emb = rela + (size_t)layer * NR2C * DDIM;
        const float* src;
        const float* W;
        float* dst;
        bool isQ;
        if (r < NR2C) {
            src = emb + (size_t)r * 64; W = Wr + layer * 512;
            dst = g_rproj + (layer * NR2C + r) * 8; isQ = false;
        } else {
            int q = r - NR2C;
            src = emb + (size_t)__ldg(relation + q) * 64; W = Wqr + layer * 512;
            dst = g_qproj + (layer * QNUM + q) * 8; isQ = true;
        }
        float2 s2 = ((const float2*)src)[lane];
        float res = 0.f;
#pragma unroll
        for (int a = 0; a < 8; a++) {
            float2 w2 = __ldg((const float2*)(W + a * 64) + lane);
            float p = s2.x * w2.x + s2.y * w2.y;
#pragma unroll
            for (int m = 16; m >= 1; m >>= 1) p += __shfl_xor_sync(0xffffffffu, p, m);
            if (lane == a) res = p;
        }
        if (lane < 8) dst[lane] = res + (isQ ? __ldg(Wqrb + layer * 8 + lane) : 0.f);
        return;
    }
    int i = (blockIdx.x - PROJ_BLOCKS) * 256 + t;
    if (i < QNUM * ENTC / 4) out4[i] = make_float4(0.f, 0.f, 0.f, 0.f);
    const int NWH = LNUM * 4096, NG = 24576, NWS = LNUM * 512, NGI = 12288;
    if (i < NWH) {
        int layer = i >> 12, ii = i & 4095;
        int e = ii & 3, lane = (ii >> 2) & 31, wc = (ii >> 7) & 3, ks = ii >> 9;
        int ntg = wc * 2 + (e >> 1), j = e & 1;
        int n = ntg * 8 + (lane >> 2), k = ks * 8 + (lane & 3) + 4 * j;
        g_bWh[i] = tf(Wh[layer * 4096 + n * 64 + k]);
    } else if (i < NWH + NG) {
        int ii = i - NWH;
        int e = ii & 3, lane = (ii >> 2) & 31;
        int ng = ii >> 7;
        int ntg = ng % 24, ks = ng / 24;
        int j = e & 1;
        const float* src = (e < 2) ? Wih : Whh;
        int n = ntg * 8 + (lane >> 2), k = ks * 8 + (lane & 3) + 4 * j;
        g_bG[ii] = tf(src[n * 64 + k]);
    } else if (i < NWH + NG + NWS) {
        int ii = i - NWH - NG;
        int layer = ii / 512, e = ii % 512;
        int j = e & 1, lane = (e >> 1) & 31, ks = e >> 6;
        int n = lane >> 2, k = ks * 8 + (lane & 3) + 4 * j;
        g_bWs[ii] = tf(Ws[layer * 512 + n * 64 + k]);
    } else if (i < NWH + NG + NWS + NGI) {
        int ii = i - NWH - NG - NWS;
        int j = ii & 1, lane = (ii >> 1) & 31;
        int ng = ii >> 6;
        int ntg = ng % 24, ks = ng / 24;
        int n = ntg * 8 + (lane >> 2), k = ks * 8 + (lane & 3) + 4 * j;
        g_bGi[ii] = tf(Wih[n * 64 + k]);
    }
}

// ---------------- layer-0 alpha table (vectorized) ---------------------------
__global__ void k_alpha0(const float* __restrict__ wal, const float* __restrict__ walb) {
    int i = blockIdx.x * blockDim.x + threadIdx.x;
    if (i >= QNUM * NR2C) return;
    int q = i / NR2C, r = i % NR2C;
    float4 r0 = __ldg((const float4*)(g_rproj + r * 8));
    float4 r1 = __ldg((const float4*)(g_rproj + r * 8) + 1);
    float4 q0 = __ldg((const float4*)(g_qproj + q * 8));
    float4 q1 = __ldg((const float4*)(g_qproj + q * 8) + 1);
    float4 w0 = __ldg((const float4*)wal);
    float4 w1 = __ldg((const float4*)wal + 1);
    float p = fmaxf(r0.x + q0.x, 0.f) * w0.x + fmaxf(r0.y + q0.y, 0.f) * w0.y
            + fmaxf(r0.z + q0.z, 0.f) * w0.z + fmaxf(r0.w + q0.w, 0.f) * w0.w
            + fmaxf(r1.x + q1.x, 0.f) * w1.x + fmaxf(r1.y + q1.y, 0.f) * w1.y
            + fmaxf(r1.z + q1.z, 0.f) * w1.z + fmaxf(r1.w + q1.w, 0.f) * w1.w;
    g_alpha0[i] = sigf(p + __ldg(walb));
}

// ---------------- edge kernels: 16 lanes/edge, full-row coalesced ------------
__global__ void k_edge0(const int* __restrict__ rel, const int* __restrict__ ridx,
                        const int* __restrict__ obj, const float* __restrict__ emb) {
    int gt = blockIdx.x * blockDim.x + threadIdx.x;
    int e = gt >> 4;
    int sl = threadIdx.x & 15;
    int r = __ldg(rel + e);
    int o = __ldg(obj + e);
    int q = __ldg(ridx + e);
    float alpha = __ldg(g_alpha0 + q * NR2C + r);
    float4 hr = __ldg((const float4*)emb + r * 16 + sl);
    asm volatile("red.global.add.v4.f32 [%0], {%1,%2,%3,%4};"
                 :: "l"(g_agg + (size_t)o * 64 + sl * 4),
                    "f"(alpha * hr.x), "f"(alpha * hr.y),
                    "f"(alpha * hr.z), "f"(alpha * hr.w) : "memory");
}

__global__ void k_edge(const int* __restrict__ sub, const int* __restrict__ rel,
                       const int* __restrict__ ridx, const int* __restrict__ obj,
                       const float* __restrict__ emb, const float* __restrict__ wal,
                       const float* __restrict__ walb, const float* __restrict__ rproj,
                       const float* __restrict__ qproj) {
    int gt = blockIdx.x * blockDim.x + threadIdx.x;
    int e = gt >> 4;
    int sl = threadIdx.x & 15;
    int r = __ldg(rel + e);
    int o = __ldg(obj + e);
    int q = __ldg(ridx + e);
    int s = __ldg(sub + e);

    float p = 0.f;
    if (sl < 8) {
        float t = __ldg(rproj + r * 8 + sl) + __ldg(qproj + q * 8 + sl)
                + g_nproj[s * 8 + sl];
        p = fmaxf(t, 0.f) * __ldg(wal + sl);
    }
    p += __shfl_xor_sync(0xffffffffu, p, 1);
    p += __shfl_xor_sync(0xffffffffu, p, 2);
    p += __shfl_xor_sync(0xffffffffu, p, 4);
    p += __shfl_xor_sync(0xffffffffu, p, 8);
    float alpha = sigf(p + __ldg(walb));

    float4 hr = __ldg((const float4*)emb + r * 16 + sl);
    float4 hs = __ldg((const float4*)g_state + (size_t)s * 16 + sl);
    asm volatile("red.global.add.v4.f32 [%0], {%1,%2,%3,%4};"
                 :: "l"(g_agg + (size_t)o * 64 + sl * 4),
                    "f"(alpha * (hs.x + hr.x)), "f"(alpha * (hs.y + hr.y)),
                    "f"(alpha * (hs.z + hr.z)), "f"(alpha * (hs.w + hr.w))
                 : "memory");
}

// ---------------- fused node phase (+nproj, +score, re-zero agg) -------------
// FIRST (light) layer prefers occ=2/128 regs; heavy layers prefer occ=3.
template <bool FIRST, bool PROJ, bool SCORE>
__global__ void __launch_bounds__(256, FIRST ? 2 : 3)
k_fused(const float* __restrict__ BWh, const float* __restrict__ BG,
        const float* __restrict__ BGi, const float* __restrict__ BWs,
        const float* __restrict__ bih, const float* __restrict__ bhh,
        const float* __restrict__ wf, const int* __restrict__ nq,
        const int* __restrict__ ne) {
    __shared__ float As[32][68];
    __shared__ float Ss[32][68];
    __shared__ float sbuf[32];
    int t = threadIdx.x;
    int warp = t >> 5, lane = t & 31;
    int wr = warp >> 2, wc = warp & 3;
    int tg = lane >> 2, tig = lane & 3;
    int m0 = blockIdx.x * 32;

    if (SCORE && t < 32) sbuf[t] = 0.f;

#pragma unroll
    for (int p = 0; p < 2; p++) {
        int idx = t + p * 256;
        int r = idx >> 4, c4 = idx & 15;
        float4 v = *((const float4*)(g_agg + (size_t)(m0 + r) * 64) + c4);
        As[r][c4 * 4 + 0] = tf(v.x);
        As[r][c4 * 4 + 1] = tf(v.y);
        As[r][c4 * 4 + 2] = tf(v.z);
        As[r][c4 * 4 + 3] = tf(v.w);
        if (!FIRST) {
            float4 s = *((const float4*)(g_state + (size_t)(m0 + r) * 64) + c4);
            Ss[r][c4 * 4 + 0] = tf(s.x);
            Ss[r][c4 * 4 + 1] = tf(s.y);
            Ss[r][c4 * 4 + 2] = tf(s.z);
            Ss[r][c4 * 4 + 3] = tf(s.w);
        }
    }
    __syncthreads();

    // zero this block's agg slice for the next layer / next replay
    {
        float4* a4 = (float4*)(g_agg + (size_t)m0 * 64);
        float4 z = make_float4(0.f, 0.f, 0.f, 0.f);
        a4[t] = z;
        a4[t + 256] = z;
    }

    // --- X = relu(agg @ Wh^T); result written back into As ---
    {
        float accx[2][4] = {};
#pragma unroll
        for (int ks = 0; ks < 8; ks++) {
            int k0 = ks * 8;
            unsigned a0 = __float_as_uint(As[wr * 16 + tg][k0 + tig]);
            unsigned a1 = __float_as_uint(As[wr * 16 + tg + 8][k0 + tig]);
            unsigned a2 = __float_as_uint(As[wr * 16 + tg][k0 + tig + 4]);
            unsigned a3 = __float_as_uint(As[wr * 16 + tg + 8][k0 + tig + 4]);
            float4 b = __ldg((const float4*)BWh + (ks * 4 + wc) * 32 + lane);
            mma8(accx[0], a0, a1, a2, a3, __float_as_uint(b.x), __float_as_uint(b.y));
            mma8(accx[1], a0, a1, a2, a3, __float_as_uint(b.z), __float_as_uint(b.w));
        }
        __syncthreads();  // all mma reads of As complete before overwrite
        int rl = wr * 16 + tg;
#pragma unroll
        for (int cg = 0; cg < 2; cg++) {
            int col = (wc * 2 + cg) * 8 + 2 * tig;
            As[rl][col]         = tf(fmaxf(accx[cg][0], 0.f));
            As[rl][col + 1]     = tf(fmaxf(accx[cg][1], 0.f));
            As[rl + 8][col]     = tf(fmaxf(accx[cg][2], 0.f));
            As[rl + 8][col + 1] = tf(fmaxf(accx[cg][3], 0.f));
        }
        __syncthreads();
    }

    // --- gates (X read from As; packed fragments) ---
    float acc_r[2][4] = {}, acc_z[2][4] = {}, acc_ni[2][4] = {}, acc_nh[2][4] = {};
#pragma unroll
    for (int ks = 0; ks < 8; ks++) {
        int k0 = ks * 8;
        unsigned x0 = __float_as_uint(As[wr * 16 + tg][k0 + tig]);
        unsigned x1 = __float_as_uint(As[wr * 16 + tg + 8][k0 + tig]);
        unsigned x2 = __float_as_uint(As[wr * 16 + tg][k0 + tig + 4]);
        unsigned x3 = __float_as_uint(As[wr * 16 + tg + 8][k0 + tig + 4]);
        unsigned s0 = 0, s1 = 0, s2 = 0, s3 = 0;
        if (!FIRST) {
            s0 = __float_as_uint(Ss[wr * 16 + tg][k0 + tig]);
            s1 = __float_as_uint(Ss[wr * 16 + tg + 8][k0 + tig]);
            s2 = __float_as_uint(Ss[wr * 16 + tg][k0 + tig + 4]);
            s3 = __float_as_uint(Ss[wr * 16 + tg + 8][k0 + tig + 4]);
        }
#pragma unroll
        for (int cg = 0; cg < 2; cg++) {
            int nb = wc * 2 + cg;
#pragma unroll
            for (int g = 0; g < 3; g++) {
                int ntg = g * 8 + nb;
                float* acc = (g == 0) ? acc_r[cg] : (g == 1) ? acc_z[cg] : acc_ni[cg];
                if (FIRST) {
                    float2 b = __ldg((const float2*)BGi + (ks * 24 + ntg) * 32 + lane);
                    mma8(acc, x0, x1, x2, x3, __float_as_uint(b.x), __float_as_uint(b.y));
                } else {
                    float4 b = __ldg((const float4*)BG + (ks * 24 + ntg) * 32 + lane);
                    mma8(acc, x0, x1, x2, x3, __float_as_uint(b.x), __float_as_uint(b.y));
                    float* acch = (g == 0) ? acc_r[cg] : (g == 1) ? acc_z[cg] : acc_nh[cg];
                    mma8(acch, s0, s1, s2, s3, __float_as_uint(b.z), __float_as_uint(b.w));
                }
            }
        }
    }

    if (PROJ) __syncthreads();  // gate-mma reads of Ss done before overwrite

    // --- GRU epilogue ---
    int r0 = m0 + wr * 16 + tg;
    float ps0 = 0.f, ps1 = 0.f;
#pragma unroll
    for (int cg = 0; cg < 2; cg++) {
        int col = (wc * 2 + cg) * 8 + 2 * tig;
        float2 bi_r = __ldg((const float2*)(bih + col));
        float2 bh_r = __ldg((const float2*)(bhh + col));
        float2 bi_z = __ldg((const float2*)(bih + 64 + col));
        float2 bh_z = __ldg((const float2*)(bhh + 64 + col));
        float2 bi_n = __ldg((const float2*)(bih + 128 + col));
        float2 bh_n = __ldg((const float2*)(bhh + 128 + col));
        float2 h0v = make_float2(0.f, 0.f), h1v = make_float2(0.f, 0.f);
        if (!FIRST) {
            h0v = *(const float2*)(g_state + (size_t)r0 * 64 + col);
            h1v = *(const float2*)(g_state + (size_t)(r0 + 8) * 64 + col);
        }
#define GRU1(ai, bx, hy, outv)                                                  \
        {                                                                       \
            float rr = sigf(acc_r[cg][ai] + bi_r.bx + bh_r.bx);                 \
            float zz = sigf(acc_z[cg][ai] + bi_z.bx + bh_z.bx);                 \
            float nn = tanhf(acc_ni[cg][ai] + bi_n.bx +                         \
                             rr * (acc_nh[cg][ai] + bh_n.bx));                  \
            outv = (1.f - zz) * nn + zz * hy;                                   \
        }
        float2 o0, o1;
        GRU1(0, x, h0v.x, o0.x)
        GRU1(1, y, h0v.y, o0.y)
        GRU1(2, x, h1v.x, o1.x)
        GRU1(3, y, h1v.y, o1.y)
#undef GRU1
        *(float2*)(g_state + (size_t)r0 * 64 + col) = o0;
        *(float2*)(g_state + (size_t)(r0 + 8) * 64 + col) = o1;
        if (PROJ) {
            int rl = wr * 16 + tg;
            Ss[rl][col] = tf(o0.x);
            Ss[rl][col + 1] = tf(o0.y);
            Ss[rl + 8][col] = tf(o1.x);
            Ss[rl + 8][col + 1] = tf(o1.y);
        }
        if (SCORE) {
            float wfa = __ldg(wf + col), wfb = __ldg(wf + col + 1);
            ps0 += o0.x * wfa + o0.y * wfb;
            ps1 += o1.x * wfa + o1.y * wfb;
        }
    }

    if (PROJ) {
        __syncthreads();
        if (warp < 2) {
            float acc[4] = {};
#pragma unroll
            for (int ks = 0; ks < 8; ks++) {
                int k0 = ks * 8;
                unsigned a0 = __float_as_uint(Ss[warp * 16 + tg][k0 + tig]);
                unsigned a1 = __float_as_uint(Ss[warp * 16 + tg + 8][k0 + tig]);
                unsigned a2 = __float_as_uint(Ss[warp * 16 + tg][k0 + tig + 4]);
                unsigned a3 = __float_as_uint(Ss[warp * 16 + tg + 8][k0 + tig + 4]);
                float2 b = *(const float2*)(BWs + ((size_t)ks * 32 + lane) * 2);
                mma8(acc, a0, a1, a2, a3, __float_as_uint(b.x), __float_as_uint(b.y));
            }
            int row = m0 + warp * 16 + tg;
            *(float2*)(g_nproj + row * 8 + 2 * tig) = make_float2(acc[0], acc[1]);
            *(float2*)(g_nproj + (row + 8) * 8 + 2 * tig) = make_float2(acc[2], acc[3]);
        }
    }

    if (SCORE) {
        int rl = wr * 16 + tg;
        atomicAdd(&sbuf[rl], ps0);
        atomicAdd(&sbuf[rl + 8], ps1);
        __syncthreads();
        if (t < 32) {
            int row = m0 + t;
            g_scores[row] = sbuf[t];
            int slot = __ldg(nq + row) * ENTC + __ldg(ne + row);
            atomicMax(&g_winner[slot], row + 1);   // +1: 0 = empty
        }
    }
}

// ---------------- merged scatter + winner reset ----------------
__global__ void k_finish(const int* __restrict__ nq, const int* __restrict__ ne,
                         float* __restrict__ out) {
    int n = blockIdx.x * blockDim.x + threadIdx.x;
    if (n >= NNODE) return;
    int slot = __ldg(nq + n) * ENTC + __ldg(ne + n);
    if (g_winner[slot] == n + 1) {
        out[slot] = g_scores[n];
        g_winner[slot] = 0;
    }
}

// ---------------- host launch ----------------
extern "C" void kernel_launch(void* const* d_in, const int* in_sizes, int n_in,
                              void* d_out, int out_size) {
    const int* relation = (const int*)d_in[0];
    const int* r_idx    = (const int*)d_in[1];
    const int* rel      = (const int*)d_in[2];
    const int* sub      = (const int*)d_in[3];
    const int* obj      = (const int*)d_in[4];
    const int* nq       = (const int*)d_in[6];
    const int* ne       = (const int*)d_in[7];
    const float* rela   = (const float*)d_in[8];
    const float* Ws     = (const float*)d_in[9];
    const float* Wr     = (const float*)d_in[10];
    const float* Wqr    = (const float*)d_in[11];
    const float* Wqrb   = (const float*)d_in[12];
    const float* wal    = (const float*)d_in[13];
    const float* walb   = (const float*)d_in[14];
    const float* Wh     = (const float*)d_in[15];
    const float* Wih    = (const float*)d_in[16];
    const float* Whh    = (const float*)d_in[17];
    const float* bih    = (const float*)d_in[18];
    const float* bhh    = (const float*)d_in[19];
    const float* Wfin   = (const float*)d_in[20];
    float* out = (float*)d_out;

    float *p_bWh, *p_bG, *p_bGi, *p_bWs, *p_rproj, *p_qproj;
    cudaGetSymbolAddress((void**)&p_bWh, g_bWh);
    cudaGetSymbolAddress((void**)&p_bG, g_bG);
    cudaGetSymbolAddress((void**)&p_bGi, g_bGi);
    cudaGetSymbolAddress((void**)&p_bWs, g_bWs);
    cudaGetSymbolAddress((void**)&p_rproj, g_rproj);
    cudaGetSymbolAddress((void**)&p_qproj, g_qproj);

    const int TB = 256;
    // launch 0: projRQ + out zero + weight fragments (one kernel, disjoint blocks)
    {
        int initBlocks = (QNUM * ENTC / 4 + TB - 1) / TB;
        k_init<<<PROJ_BLOCKS + initBlocks, TB>>>((float4*)out, Wh, Wih, Whh, Ws,
                                                 rela, Wr, Wqr, Wqrb, relation);
    }
    // launch 1: layer-0 alpha table
    k_alpha0<<<(QNUM * NR2C + TB - 1) / TB, TB>>>(wal, walb);

    const int EG = ENUM * 16 / TB;
    const int FG = NNODE / 32;
    for (int i = 0; i < LNUM; i++) {
        const float* emb = rela + (size_t)i * NR2C * DDIM;
        const float* rp = p_rproj + i * NR2C * ADIM;
        const float* qp = p_qproj + i * QNUM * ADIM;
        if (i == 0) {
            k_edge0<<<EG, TB>>>(rel, r_idx, obj, emb);
            k_fused<true, true, false><<<FG, TB>>>(p_bWh, p_bG, p_bGi, p_bWs + 512,
                                                   bih, bhh, Wfin, nq, ne);
        } else {
            k_edge<<<EG, TB>>>(
                sub + (size_t)i * ENUM, rel + (size_t)i * ENUM, r_idx + (size_t)i * ENUM,
                obj + (size_t)i * ENUM, emb, wal + i * 8, walb + i, rp, qp);
            if (i + 1 < LNUM)
                k_fused<false, true, false><<<FG, TB>>>(p_bWh + i * 4096, p_bG, p_bGi,
                                                        p_bWs + (i + 1) * 512,
                                                        bih, bhh, Wfin, nq, ne);
            else
                k_fused<false, false, true><<<FG, TB>>>(p_bWh + i * 4096, p_bG, p_bGi,
                                                        p_bWs, bih, bhh, Wfin, nq, ne);
        }
    }

    k_finish<<<(NNODE + TB - 1) / TB, TB>>>(nq, ne, out);
}

// round 17
// speedup vs baseline: 1.3029x; 1.2784x over previous
#include <cuda_runtime.h>
#include <cuda_fp16.h>

#define LNUM 3
#define ENUM 1000000
#define NNODE 100000
#define DDIM 64
#define ADIM 8
#define NR2C 461
#define QNUM 1000
#define ENTC 10000

// ---------------- scratch (device globals; no allocation) ----------------
__device__ float  g_state[NNODE * DDIM];
__device__ __half g_aggh[NNODE * DDIM];    // fp16 accumulator; re-zeroed by k_fused
__device__ float  g_nproj[NNODE * ADIM];
__device__ float  g_rproj[LNUM * NR2C * ADIM];
__device__ float  g_qproj[LNUM * QNUM * ADIM];
__device__ float  g_alpha0[QNUM * NR2C];
__device__ float  g_bWh[LNUM * 4096];      // [ks][wc][lane][4]: cg0(j0,j1), cg1(j0,j1)
__device__ float  g_bG[24576];             // [ks][ntg][lane][4]: Wih(j0,j1), Whh(j0,j1)
__device__ float  g_bGi[12288];            // [ks][ntg][lane][2]: Wih only (dense, FIRST)
__device__ float  g_bWs[LNUM * 512];
__device__ float  g_scores[NNODE];
__device__ int    g_winner[QNUM * ENTC];   // zero at load; winner(+1) reset by k_finish

// ---------------- helpers ----------------
__device__ __forceinline__ unsigned f2tf(float x) {
    unsigned u;
    asm("cvt.rna.tf32.f32 %0, %1;" : "=r"(u) : "f"(x));
    return u;
}
__device__ __forceinline__ float tf(float x) { return __uint_as_float(f2tf(x)); }
__device__ __forceinline__ float sigf(float x) { return 1.f / (1.f + __expf(-x)); }
__device__ __forceinline__ unsigned packh2(float lo, float hi) {
    unsigned u;
    asm("cvt.rn.f16x2.f32 %0, %1, %2;" : "=r"(u) : "f"(hi), "f"(lo));
    return u;
}

__device__ __forceinline__ void mma8(float acc[4], unsigned a0, unsigned a1,
                                     unsigned a2, unsigned a3, unsigned b0, unsigned b1) {
    asm volatile(
        "mma.sync.aligned.m16n8k8.row.col.f32.tf32.tf32.f32 "
        "{%0,%1,%2,%3}, {%4,%5,%6,%7}, {%8,%9}, {%0,%1,%2,%3};"
        : "+f"(acc[0]), "+f"(acc[1]), "+f"(acc[2]), "+f"(acc[3])
        : "r"(a0), "r"(a1), "r"(a2), "r"(a3), "r"(b0), "r"(b1));
}

// ---------------- combined init: projRQ (blocks [0,PB)) + zero/pack rest -----
#define PROJ_BLOCKS 548   // ceil(LNUM*(NR2C+QNUM)*32 / 256)

__global__ void k_init(float4* out4, const float* __restrict__ Wh,
                       const float* __restrict__ Wih, const float* __restrict__ Whh,
                       const float* __restrict__ Ws, const float* __restrict__ rela,
                       const float* __restrict__ Wr, const float* __restrict__ Wqr,
                       const float* __restrict__ Wqrb, const int* __restrict__ relation) {
    int t = threadIdx.x;
    if (blockIdx.x < PROJ_BLOCKS) {
        int w = (blockIdx.x * 256 + t) >> 5;
        int lane = t & 31;
        const int PER = NR2C + QNUM;
        if (w >= LNUM * PER) return;
        int layer = w / PER;
        int r = w % PER;
        const float* emb = rela + (size_t)layer * NR2C * DDIM;
        const float* src;
        const float* W;
        float* dst;
        bool isQ;
        if (r < NR2C) {
            src = emb + (size_t)r * 64; W = Wr + layer * 512;
            dst = g_rproj + (layer * NR2C + r) * 8; isQ = false;
        } else {
            int q = r - NR2C;
            src = emb + (size_t)__ldg(relation + q) * 64; W = Wqr + layer * 512;
            dst = g_qproj + (layer * QNUM + q) * 8; isQ = true;
        }
        float2 s2 = ((const float2*)src)[lane];
        float res = 0.f;
#pragma unroll
        for (int a = 0; a < 8; a++) {
            float2 w2 = __ldg((const float2*)(W + a * 64) + lane);
            float p = s2.x * w2.x + s2.y * w2.y;
#pragma unroll
            for (int m = 16; m >= 1; m >>= 1) p += __shfl_xor_sync(0xffffffffu, p, m);
            if (lane == a) res = p;
        }
        if (lane < 8) dst[lane] = res + (isQ ? __ldg(Wqrb + layer * 8 + lane) : 0.f);
        return;
    }
    int i = (blockIdx.x - PROJ_BLOCKS) * 256 + t;
    if (i < QNUM * ENTC / 4) out4[i] = make_float4(0.f, 0.f, 0.f, 0.f);
    const int NWH = LNUM * 4096, NG = 24576, NWS = LNUM * 512, NGI = 12288;
    if (i < NWH) {
        int layer = i >> 12, ii = i & 4095;
        int e = ii & 3, lane = (ii >> 2) & 31, wc = (ii >> 7) & 3, ks = ii >> 9;
        int ntg = wc * 2 + (e >> 1), j = e & 1;
        int n = ntg * 8 + (lane >> 2), k = ks * 8 + (lane & 3) + 4 * j;
        g_bWh[i] = tf(Wh[layer * 4096 + n * 64 + k]);
    } else if (i < NWH + NG) {
        int ii = i - NWH;
        int e = ii & 3, lane = (ii >> 2) & 31;
        int ng = ii >> 7;
        int ntg = ng % 24, ks = ng / 24;
        int j = e & 1;
        const float* src = (e < 2) ? Wih : Whh;
        int n = ntg * 8 + (lane >> 2), k = ks * 8 + (lane & 3) + 4 * j;
        g_bG[ii] = tf(src[n * 64 + k]);
    } else if (i < NWH + NG + NWS) {
        int ii = i - NWH - NG;
        int layer = ii / 512, e = ii % 512;
        int j = e & 1, lane = (e >> 1) & 31, ks = e >> 6;
        int n = lane >> 2, k = ks * 8 + (lane & 3) + 4 * j;
        g_bWs[ii] = tf(Ws[layer * 512 + n * 64 + k]);
    } else if (i < NWH + NG + NWS + NGI) {
        int ii = i - NWH - NG - NWS;
        int j = ii & 1, lane = (ii >> 1) & 31;
        int ng = ii >> 6;
        int ntg = ng % 24, ks = ng / 24;
        int n = ntg * 8 + (lane >> 2), k = ks * 8 + (lane & 3) + 4 * j;
        g_bGi[ii] = tf(Wih[n * 64 + k]);
    }
}

// ---------------- layer-0 alpha table (vectorized) ---------------------------
__global__ void k_alpha0(const float* __restrict__ wal, const float* __restrict__ walb) {
    int i = blockIdx.x * blockDim.x + threadIdx.x;
    if (i >= QNUM * NR2C) return;
    int q = i / NR2C, r = i % NR2C;
    float4 r0 = __ldg((const float4*)(g_rproj + r * 8));
    float4 r1 = __ldg((const float4*)(g_rproj + r * 8) + 1);
    float4 q0 = __ldg((const float4*)(g_qproj + q * 8));
    float4 q1 = __ldg((const float4*)(g_qproj + q * 8) + 1);
    float4 w0 = __ldg((const float4*)wal);
    float4 w1 = __ldg((const float4*)wal + 1);
    float p = fmaxf(r0.x + q0.x, 0.f) * w0.x + fmaxf(r0.y + q0.y, 0.f) * w0.y
            + fmaxf(r0.z + q0.z, 0.f) * w0.z + fmaxf(r0.w + q0.w, 0.f) * w0.w
            + fmaxf(r1.x + q1.x, 0.f) * w1.x + fmaxf(r1.y + q1.y, 0.f) * w1.y
            + fmaxf(r1.z + q1.z, 0.f) * w1.z + fmaxf(r1.w + q1.w, 0.f) * w1.w;
    g_alpha0[i] = sigf(p + __ldg(walb));
}

// ---------------- edge kernels: 8 lanes/edge, fp16 v4 atomics ----------------
__global__ void k_edge0(const int* __restrict__ rel, const int* __restrict__ ridx,
                        const int* __restrict__ obj, const float* __restrict__ emb) {
    int gt = blockIdx.x * blockDim.x + threadIdx.x;
    int e = gt >> 3;
    int sl = threadIdx.x & 7;
    int r = __ldg(rel + e);
    int o = __ldg(obj + e);
    int q = __ldg(ridx + e);
    float alpha = __ldg(g_alpha0 + q * NR2C + r);
    const float4* hr4 = (const float4*)emb + r * 16 + sl * 2;
    float4 ha = __ldg(hr4), hb = __ldg(hr4 + 1);
    unsigned u0 = packh2(alpha * ha.x, alpha * ha.y);
    unsigned u1 = packh2(alpha * ha.z, alpha * ha.w);
    unsigned u2 = packh2(alpha * hb.x, alpha * hb.y);
    unsigned u3 = packh2(alpha * hb.z, alpha * hb.w);
    asm volatile("red.global.add.noftz.v4.f16x2 [%0], {%1,%2,%3,%4};"
                 :: "l"(g_aggh + (size_t)o * 64 + sl * 8),
                    "r"(u0), "r"(u1), "r"(u2), "r"(u3) : "memory");
}

__global__ void k_edge(const int* __restrict__ sub, const int* __restrict__ rel,
                       const int* __restrict__ ridx, const int* __restrict__ obj,
                       const float* __restrict__ emb, const float* __restrict__ wal,
                       const float* __restrict__ walb, const float* __restrict__ rproj,
                       const float* __restrict__ qproj) {
    int gt = blockIdx.x * blockDim.x + threadIdx.x;
    int e = gt >> 3;
    int sl = threadIdx.x & 7;
    int r = __ldg(rel + e);
    int o = __ldg(obj + e);
    int q = __ldg(ridx + e);
    int s = __ldg(sub + e);

    float tt = __ldg(rproj + r * 8 + sl) + __ldg(qproj + q * 8 + sl)
             + g_nproj[s * 8 + sl];
    float p = fmaxf(tt, 0.f) * __ldg(wal + sl);
    p += __shfl_xor_sync(0xffffffffu, p, 1, 8);
    p += __shfl_xor_sync(0xffffffffu, p, 2, 8);
    p += __shfl_xor_sync(0xffffffffu, p, 4, 8);
    float alpha = sigf(p + __ldg(walb));

    const float4* hr4 = (const float4*)emb + r * 16 + sl * 2;
    float4 ha = __ldg(hr4), hb = __ldg(hr4 + 1);
    const float4* hs4 = (const float4*)g_state + (size_t)s * 16 + sl * 2;
    float4 sa = __ldg(hs4), sb = __ldg(hs4 + 1);
    unsigned u0 = packh2(alpha * (sa.x + ha.x), alpha * (sa.y + ha.y));
    unsigned u1 = packh2(alpha * (sa.z + ha.z), alpha * (sa.w + ha.w));
    unsigned u2 = packh2(alpha * (sb.x + hb.x), alpha * (sb.y + hb.y));
    unsigned u3 = packh2(alpha * (sb.z + hb.z), alpha * (sb.w + hb.w));
    asm volatile("red.global.add.noftz.v4.f16x2 [%0], {%1,%2,%3,%4};"
                 :: "l"(g_aggh + (size_t)o * 64 + sl * 8),
                    "r"(u0), "r"(u1), "r"(u2), "r"(u3) : "memory");
}

// ---------------- fused node phase (+nproj, +score, re-zero agg) -------------
template <bool FIRST, bool PROJ, bool SCORE>
__global__ void __launch_bounds__(256, FIRST ? 2 : 3)
k_fused(const float* __restrict__ BWh, const float* __restrict__ BG,
        const float* __restrict__ BGi, const float* __restrict__ BWs,
        const float* __restrict__ bih, const float* __restrict__ bhh,
        const float* __restrict__ wf, const int* __restrict__ nq,
        const int* __restrict__ ne) {
    __shared__ float As[32][68];
    __shared__ float Ss[32][68];
    __shared__ float sbuf[32];
    int t = threadIdx.x;
    int warp = t >> 5, lane = t & 31;
    int wr = warp >> 2, wc = warp & 3;
    int tg = lane >> 2, tig = lane & 3;
    int m0 = blockIdx.x * 32;

    if (SCORE && t < 32) sbuf[t] = 0.f;

#pragma unroll
    for (int p = 0; p < 2; p++) {
        int idx = t + p * 256;
        int r = idx >> 4, c4 = idx & 15;
        uint2 v = *((const uint2*)(g_aggh + (size_t)(m0 + r) * 64) + c4);
        float2 f0 = __half22float2(*(__half2*)&v.x);
        float2 f1 = __half22float2(*(__half2*)&v.y);
        As[r][c4 * 4 + 0] = tf(f0.x);
        As[r][c4 * 4 + 1] = tf(f0.y);
        As[r][c4 * 4 + 2] = tf(f1.x);
        As[r][c4 * 4 + 3] = tf(f1.y);
        if (!FIRST) {
            float4 s = *((const float4*)(g_state + (size_t)(m0 + r) * 64) + c4);
            Ss[r][c4 * 4 + 0] = tf(s.x);
            Ss[r][c4 * 4 + 1] = tf(s.y);
            Ss[r][c4 * 4 + 2] = tf(s.z);
            Ss[r][c4 * 4 + 3] = tf(s.w);
        }
    }
    __syncthreads();

    // zero this block's fp16 agg slice (32 rows x 128B = 4KB) for next layer
    {
        float4* a4 = (float4*)(g_aggh + (size_t)m0 * 64);
        a4[t] = make_float4(0.f, 0.f, 0.f, 0.f);
    }

    // --- X = relu(agg @ Wh^T); result written back into As ---
    {
        float accx[2][4] = {};
#pragma unroll
        for (int ks = 0; ks < 8; ks++) {
            int k0 = ks * 8;
            unsigned a0 = __float_as_uint(As[wr * 16 + tg][k0 + tig]);
            unsigned a1 = __float_as_uint(As[wr * 16 + tg + 8][k0 + tig]);
            unsigned a2 = __float_as_uint(As[wr * 16 + tg][k0 + tig + 4]);
            unsigned a3 = __float_as_uint(As[wr * 16 + tg + 8][k0 + tig + 4]);
            float4 b = __ldg((const float4*)BWh + (ks * 4 + wc) * 32 + lane);
            mma8(accx[0], a0, a1, a2, a3, __float_as_uint(b.x), __float_as_uint(b.y));
            mma8(accx[1], a0, a1, a2, a3, __float_as_uint(b.z), __float_as_uint(b.w));
        }
        __syncthreads();  // all mma reads of As complete before overwrite
        int rl = wr * 16 + tg;
#pragma unroll
        for (int cg = 0; cg < 2; cg++) {
            int col = (wc * 2 + cg) * 8 + 2 * tig;
            As[rl][col]         = tf(fmaxf(accx[cg][0], 0.f));
            As[rl][col + 1]     = tf(fmaxf(accx[cg][1], 0.f));
            As[rl + 8][col]     = tf(fmaxf(accx[cg][2], 0.f));
            As[rl + 8][col + 1] = tf(fmaxf(accx[cg][3], 0.f));
        }
        __syncthreads();
    }

    // --- gates (X read from As; packed fragments) ---
    float acc_r[2][4] = {}, acc_z[2][4] = {}, acc_ni[2][4] = {}, acc_nh[2][4] = {};
#pragma unroll
    for (int ks = 0; ks < 8; ks++) {
        int k0 = ks * 8;
        unsigned x0 = __float_as_uint(As[wr * 16 + tg][k0 + tig]);
        unsigned x1 = __float_as_uint(As[wr * 16 + tg + 8][k0 + tig]);
        unsigned x2 = __float_as_uint(As[wr * 16 + tg][k0 + tig + 4]);
        unsigned x3 = __float_as_uint(As[wr * 16 + tg + 8][k0 + tig + 4]);
        unsigned s0 = 0, s1 = 0, s2 = 0, s3 = 0;
        if (!FIRST) {
            s0 = __float_as_uint(Ss[wr * 16 + tg][k0 + tig]);
            s1 = __float_as_uint(Ss[wr * 16 + tg + 8][k0 + tig]);
            s2 = __float_as_uint(Ss[wr * 16 + tg][k0 + tig + 4]);
            s3 = __float_as_uint(Ss[wr * 16 + tg + 8][k0 + tig + 4]);
        }
#pragma unroll
        for (int cg = 0; cg < 2; cg++) {
            int nb = wc * 2 + cg;
#pragma unroll
            for (int g = 0; g < 3; g++) {
                int ntg = g * 8 + nb;
                float* acc = (g == 0) ? acc_r[cg] : (g == 1) ? acc_z[cg] : acc_ni[cg];
                if (FIRST) {
                    float2 b = __ldg((const float2*)BGi + (ks * 24 + ntg) * 32 + lane);
                    mma8(acc, x0, x1, x2, x3, __float_as_uint(b.x), __float_as_uint(b.y));
                } else {
                    float4 b = __ldg((const float4*)BG + (ks * 24 + ntg) * 32 + lane);
                    mma8(acc, x0, x1, x2, x3, __float_as_uint(b.x), __float_as_uint(b.y));
                    float* acch = (g == 0) ? acc_r[cg] : (g == 1) ? acc_z[cg] : acc_nh[cg];
                    mma8(acch, s0, s1, s2, s3, __float_as_uint(b.z), __float_as_uint(b.w));
                }
            }
        }
    }

    if (PROJ) __syncthreads();  // gate-mma reads of Ss done before overwrite

    // --- GRU epilogue ---
    int r0 = m0 + wr * 16 + tg;
    float ps0 = 0.f, ps1 = 0.f;
#pragma unroll
    for (int cg = 0; cg < 2; cg++) {
        int col = (wc * 2 + cg) * 8 + 2 * tig;
        float2 bi_r = __ldg((const float2*)(bih + col));
        float2 bh_r = __ldg((const float2*)(bhh + col));
        float2 bi_z = __ldg((const float2*)(bih + 64 + col));
        float2 bh_z = __ldg((const float2*)(bhh + 64 + col));
        float2 bi_n = __ldg((const float2*)(bih + 128 + col));
        float2 bh_n = __ldg((const float2*)(bhh + 128 + col));
        float2 h0v = make_float2(0.f, 0.f), h1v = make_float2(0.f, 0.f);
        if (!FIRST) {
            h0v = *(const float2*)(g_state + (size_t)r0 * 64 + col);
            h1v = *(const float2*)(g_state + (size_t)(r0 + 8) * 64 + col);
        }
#define GRU1(ai, bx, hy, outv)                                                  \
        {                                                                       \
            float rr = sigf(acc_r[cg][ai] + bi_r.bx + bh_r.bx);                 \
            float zz = sigf(acc_z[cg][ai] + bi_z.bx + bh_z.bx);                 \
            float nn = tanhf(acc_ni[cg][ai] + bi_n.bx +                         \
                             rr * (acc_nh[cg][ai] + bh_n.bx));                  \
            outv = (1.f - zz) * nn + zz * hy;                                   \
        }
        float2 o0, o1;
        GRU1(0, x, h0v.x, o0.x)
        GRU1(1, y, h0v.y, o0.y)
        GRU1(2, x, h1v.x, o1.x)
        GRU1(3, y, h1v.y, o1.y)
#undef GRU1
        *(float2*)(g_state + (size_t)r0 * 64 + col) = o0;
        *(float2*)(g_state + (size_t)(r0 + 8) * 64 + col) = o1;
        if (PROJ) {
            int rl = wr * 16 + tg;
            Ss[rl][col] = tf(o0.x);
            Ss[rl][col + 1] = tf(o0.y);
            Ss[rl + 8][col] = tf(o1.x);
            Ss[rl + 8][col + 1] = tf(o1.y);
        }
        if (SCORE) {
            float wfa = __ldg(wf + col), wfb = __ldg(wf + col + 1);
            ps0 += o0.x * wfa + o0.y * wfb;
            ps1 += o1.x * wfa + o1.y * wfb;
        }
    }

    if (PROJ) {
        __syncthreads();
        if (warp < 2) {
            float acc[4] = {};
#pragma unroll
            for (int ks = 0; ks < 8; ks++) {
                int k0 = ks * 8;
                unsigned a0 = __float_as_uint(Ss[warp * 16 + tg][k0 + tig]);
                unsigned a1 = __float_as_uint(Ss[warp * 16 + tg + 8][k0 + tig]);
                unsigned a2 = __float_as_uint(Ss[warp * 16 + tg][k0 + tig + 4]);
                unsigned a3 = __float_as_uint(Ss[warp * 16 + tg + 8][k0 + tig + 4]);
                float2 b = *(const float2*)(BWs + ((size_t)ks * 32 + lane) * 2);
                mma8(acc, a0, a1, a2, a3, __float_as_uint(b.x), __float_as_uint(b.y));
            }
            int row = m0 + warp * 16 + tg;
            *(float2*)(g_nproj + row * 8 + 2 * tig) = make_float2(acc[0], acc[1]);
            *(float2*)(g_nproj + (row + 8) * 8 + 2 * tig) = make_float2(acc[2], acc[3]);
        }
    }

    if (SCORE) {
        int rl = wr * 16 + tg;
        atomicAdd(&sbuf[rl], ps0);
        atomicAdd(&sbuf[rl + 8], ps1);
        __syncthreads();
        if (t < 32) {
            int row = m0 + t;
            g_scores[row] = sbuf[t];
            int slot = __ldg(nq + row) * ENTC + __ldg(ne + row);
            atomicMax(&g_winner[slot], row + 1);   // +1: 0 = empty
        }
    }
}

// ---------------- merged scatter + winner reset ----------------
__global__ void k_finish(const int* __restrict__ nq, const int* __restrict__ ne,
                         float* __restrict__ out) {
    int n = blockIdx.x * blockDim.x + threadIdx.x;
    if (n >= NNODE) return;
    int slot = __ldg(nq + n) * ENTC + __ldg(ne + n);
    if (g_winner[slot] == n + 1) {
        out[slot] = g_scores[n];
        g_winner[slot] = 0;
    }
}

// ---------------- host launch ----------------
extern "C" void kernel_launch(void* const* d_in, const int* in_sizes, int n_in,
                              void* d_out, int out_size) {
    const int* relation = (const int*)d_in[0];
    const int* r_idx    = (const int*)d_in[1];
    const int* rel      = (const int*)d_in[2];
    const int* sub      = (const int*)d_in[3];
    const int* obj      = (const int*)d_in[4];
    const int* nq       = (const int*)d_in[6];
    const int* ne       = (const int*)d_in[7];
    const float* rela   = (const float*)d_in[8];
    const float* Ws     = (const float*)d_in[9];
    const float* Wr     = (const float*)d_in[10];
    const float* Wqr    = (const float*)d_in[11];
    const float* Wqrb   = (const float*)d_in[12];
    const float* wal    = (const float*)d_in[13];
    const float* walb   = (const float*)d_in[14];
    const float* Wh     = (const float*)d_in[15];
    const float* Wih    = (const float*)d_in[16];
    const float* Whh    = (const float*)d_in[17];
    const float* bih    = (const float*)d_in[18];
    const float* bhh    = (const float*)d_in[19];
    const float* Wfin   = (const float*)d_in[20];
    float* out = (float*)d_out;

    float *p_bWh, *p_bG, *p_bGi, *p_bWs, *p_rproj, *p_qproj;
    cudaGetSymbolAddress((void**)&p_bWh, g_bWh);
    cudaGetSymbolAddress((void**)&p_bG, g_bG);
    cudaGetSymbolAddress((void**)&p_bGi, g_bGi);
    cudaGetSymbolAddress((void**)&p_bWs, g_bWs);
    cudaGetSymbolAddress((void**)&p_rproj, g_rproj);
    cudaGetSymbolAddress((void**)&p_qproj, g_qproj);

    const int TB = 256;
    {
        int initBlocks = (QNUM * ENTC / 4 + TB - 1) / TB;
        k_init<<<PROJ_BLOCKS + initBlocks, TB>>>((float4*)out, Wh, Wih, Whh, Ws,
                                                 rela, Wr, Wqr, Wqrb, relation);
    }
    k_alpha0<<<(QNUM * NR2C + TB - 1) / TB, TB>>>(wal, walb);

    const int EG = ENUM * 8 / TB;   // 31250 blocks, exact
    const int FG = NNODE / 32;
    for (int i = 0; i < LNUM; i++) {
        const float* emb = rela + (size_t)i * NR2C * DDIM;
        const float* rp = p_rproj + i * NR2C * ADIM;
        const float* qp = p_qproj + i * QNUM * ADIM;
        if (i == 0) {
            k_edge0<<<EG, TB>>>(rel, r_idx, obj, emb);
            k_fused<true, true, false><<<FG, TB>>>(p_bWh, p_bG, p_bGi, p_bWs + 512,
                                                   bih, bhh, Wfin, nq, ne);
        } else {
            k_edge<<<EG, TB>>>(
                sub + (size_t)i * ENUM, rel + (size_t)i * ENUM, r_idx + (size_t)i * ENUM,
                obj + (size_t)i * ENUM, emb, wal + i * 8, walb + i, rp, qp);
            if (i + 1 < LNUM)
                k_fused<false, true, false><<<FG, TB>>>(p_bWh + i * 4096, p_bG, p_bGi,
                                                        p_bWs + (i + 1) * 512,
                                                        bih, bhh, Wfin, nq, ne);
            else
                k_fused<false, false, true><<<FG, TB>>>(p_bWh + i * 4096, p_bG, p_bGi,
                                                        p_bWs, bih, bhh, Wfin, nq, ne);
        }
    }

    k_finish<<<(NNODE + TB - 1) / TB, TB>>>(nq, ne, out);
}